// round 7
// baseline (speedup 1.0000x reference)
#include <cuda_runtime.h>

// x:      (4, 64, 128, 128) fp32  -> 256 independent 128x128 images
// weight: (4, 576, 128, 128) fp32 -> 9 taps per channel, tap k strided by H*W
// steps = 8
//
// Persistent CTAs (1/SM), 512 threads, V=2 (warp owns region rows 2g,2g+1,
// own rows in registers, vertical neighbors via smem ping-pong), packed
// fma.rn.f32x2 stencil (round-5 body, the measured best).
// Round 7 delta vs round 5 (62.6us): NO smem staging for weights/x.
//   - prologue loads weights+x straight to registers with LDG.128
//   - next tile's 164KB warmed into L2 with cp.async.bulk.prefetch.L2.global
//     (hint only: no smem, no mbarrier), issue spread over 10 warps
//   -> removes ~294KB/tile of smem crossbar traffic (TMA-write + LDS-read)

#define H      128
#define W      128
#define IMG    (H * W)
#define STEPS  8
#define TH     16
#define NT     2048
#define SROWS  34

typedef unsigned long long u64;
typedef unsigned int u32;

__device__ __forceinline__ u64 pk(float lo, float hi) {
    u64 r; asm("mov.b64 %0, {%1,%2};" : "=l"(r) : "f"(lo), "f"(hi)); return r;
}
__device__ __forceinline__ void upk(u64 v, float& lo, float& hi) {
    asm("mov.b64 {%0,%1}, %2;" : "=f"(lo), "=f"(hi) : "l"(v));
}
__device__ __forceinline__ void fma2(u64& d, u64 a, u64 b) {
    asm("fma.rn.f32x2 %0, %1, %2, %0;" : "+l"(d) : "l"(a), "l"(b));
}
__device__ __forceinline__ float shup(float v) { return __shfl_up_sync(0xffffffffu, v, 1); }
__device__ __forceinline__ float shdn(float v) { return __shfl_down_sync(0xffffffffu, v, 1); }

__device__ __forceinline__ void l2pf(const void* p, u32 bytes) {
    asm volatile("cp.async.bulk.prefetch.L2.global [%0], %1;"
                 :: "l"(p), "r"(bytes) : "memory");
}

// Distributed L2 prefetch: issuer k (0..8 = weight tap k, 9 = x) warms the
// next tile's region rows into L2. Pure hint; no completion tracking.
__device__ __forceinline__ void issue_prefetch_k(int t, int k,
                                                 const float* x, const float* wgt) {
    const int t0  = (t & 7) * TH;
    const int img = t >> 3;
    const int rlo = (t0 - 8 < 0) ? 0 : (t0 - 8);
    const int rhi = (t0 + 24 > H) ? H : (t0 + 24);
    const u32 bytes = (u32)(rhi - rlo) * (W * 4);
    if (k < 9) {
        l2pf(wgt + ((size_t)(img * 9 + k) << 14) + rlo * W, bytes);
    } else {
        l2pf(x + ((size_t)img << 14) + rlo * W, bytes);
    }
}

__global__ __launch_bounds__(512, 1)
void diffusion_persist_kernel(const float* __restrict__ x,
                              const float* __restrict__ wgt,
                              float* __restrict__ out)
{
    __shared__ float buf[2][SROWS][W];

    const int tid  = threadIdx.x;
    const int lane = tid & 31;
    const int warp = tid >> 5;          // 0..15; owns region rows 2g, 2g+1
    const int col0 = lane << 2;
    const int g2   = warp * 2;
    const bool issuer = (lane == 0 && warp < 10);

    // one-time: guard rows (region rows -1 and 32 stay zero forever)
    if (tid < 128) {
        int b = tid >> 6, r = (tid >> 5) & 1;
        *(float4*)&buf[b][r ? (SROWS - 1) : 0][col0] = make_float4(0.f, 0.f, 0.f, 0.f);
    }
    __syncthreads();

    int t = blockIdx.x;
    const int stride = gridDim.x;
    if (issuer && t < NT) issue_prefetch_k(t, warp, x, wgt);

    for (; t < NT; t += stride) {
        const int img = t >> 3;
        const int t0  = (t & 7) * TH;

        // ---- prologue: LDG weights -> normalized packed regs; LDG x rows
        u64 Wp[2][3][6];
        float4 y0, y1;
#pragma unroll
        for (int ro = 0; ro < 2; ro++) {
            const int rr   = g2 + ro;
            const int grow = t0 - 8 + rr;
            const bool rv  = ((unsigned)grow < (unsigned)H);
            float aa[9][4];
            if (rv) {
                const float* wb = wgt + ((size_t)img * 9 << 14) + grow * W + col0;
                float s0 = 0.f, s1 = 0.f, s2 = 0.f, s3 = 0.f;
#pragma unroll
                for (int k = 0; k < 9; k++) {
                    float4 tv = __ldg(reinterpret_cast<const float4*>(wb + ((size_t)k << 14)));
                    aa[k][0] = fabsf(tv.x); aa[k][1] = fabsf(tv.y);
                    aa[k][2] = fabsf(tv.z); aa[k][3] = fabsf(tv.w);
                    s0 += aa[k][0]; s1 += aa[k][1]; s2 += aa[k][2]; s3 += aa[k][3];
                }
                const float i0 = __fdividef(1.f, s0), i1 = __fdividef(1.f, s1);
                const float i2 = __fdividef(1.f, s2), i3 = __fdividef(1.f, s3);
#pragma unroll
                for (int k = 0; k < 9; k++) {
                    aa[k][0] *= i0; aa[k][1] *= i1; aa[k][2] *= i2; aa[k][3] *= i3;
                }
                if (lane == 0)  { aa[0][0] = 0.f; aa[3][0] = 0.f; aa[6][0] = 0.f; }
                if (lane == 31) { aa[2][3] = 0.f; aa[5][3] = 0.f; aa[8][3] = 0.f; }
            } else {
#pragma unroll
                for (int k = 0; k < 9; k++) {
                    aa[k][0] = 0.f; aa[k][1] = 0.f; aa[k][2] = 0.f; aa[k][3] = 0.f;
                }
            }
#pragma unroll
            for (int ki = 0; ki < 3; ki++) {
                Wp[ro][ki][0] = pk(aa[ki * 3 + 0][0], aa[ki * 3 + 0][1]);
                Wp[ro][ki][1] = pk(aa[ki * 3 + 1][0], aa[ki * 3 + 1][1]);
                Wp[ro][ki][2] = pk(aa[ki * 3 + 2][0], aa[ki * 3 + 2][1]);
                Wp[ro][ki][3] = pk(aa[ki * 3 + 0][2], aa[ki * 3 + 0][3]);
                Wp[ro][ki][4] = pk(aa[ki * 3 + 1][2], aa[ki * 3 + 1][3]);
                Wp[ro][ki][5] = pk(aa[ki * 3 + 2][2], aa[ki * 3 + 2][3]);
            }
            float4 xv = make_float4(0.f, 0.f, 0.f, 0.f);
            if (rv) xv = __ldg(reinterpret_cast<const float4*>(
                                   x + ((size_t)img << 14) + grow * W + col0));
            if (ro == 0) y0 = xv; else y1 = xv;
            *(float4*)&buf[0][rr + 1][col0] = xv;
        }
        __syncthreads();   // buf[0] fully published
        // Note: prologue's buf[0] writes are safe vs the previous tile:
        // step 7 reads only buf[1]; the last buf[0] reads were step 6,
        // fenced by the step-6 __syncthreads.

        // warm L2 for the next tile (overlaps the 8-step loop)
        if (issuer && t + stride < NT) issue_prefetch_k(t + stride, warp, x, wgt);

        // ---- 8 fused steps (round-5 body)
#pragma unroll
        for (int s = 0; s < STEPS; s++) {
            const int cb = s & 1;
            float4 va = *(const float4*)&buf[cb][g2][col0];      // row 2g-1
            float4 vb = *(const float4*)&buf[cb][g2 + 3][col0];  // row 2g+2

            const float xl0 = shup(y0.w), xr0 = shdn(y0.x);
            const float xl1 = shup(y1.w), xr1 = shdn(y1.x);
            const float xlA = shup(va.w), xrA = shdn(va.x);
            const float xlB = shup(vb.w), xrB = shdn(vb.x);

            const u64 pA0 = pk(xlA, va.x), pA1 = pk(va.x, va.y), pA2 = pk(va.y, va.z);
            const u64 pA3 = pk(va.z, va.w), pA4 = pk(va.w, xrA);
            const u64 p00 = pk(xl0, y0.x), p01 = pk(y0.x, y0.y), p02 = pk(y0.y, y0.z);
            const u64 p03 = pk(y0.z, y0.w), p04 = pk(y0.w, xr0);
            const u64 p10 = pk(xl1, y1.x), p11 = pk(y1.x, y1.y), p12 = pk(y1.y, y1.z);
            const u64 p13 = pk(y1.z, y1.w), p14 = pk(y1.w, xr1);
            const u64 pB0 = pk(xlB, vb.x), pB1 = pk(vb.x, vb.y), pB2 = pk(vb.y, vb.z);
            const u64 pB3 = pk(vb.z, vb.w), pB4 = pk(vb.w, xrB);

            u64 n001 = 0ull, n023 = 0ull, n101 = 0ull, n123 = 0ull;
            fma2(n001, Wp[0][0][0], pA0); fma2(n023, Wp[0][0][3], pA2);
            fma2(n101, Wp[1][0][0], p00); fma2(n123, Wp[1][0][3], p02);
            fma2(n001, Wp[0][0][1], pA1); fma2(n023, Wp[0][0][4], pA3);
            fma2(n101, Wp[1][0][1], p01); fma2(n123, Wp[1][0][4], p03);
            fma2(n001, Wp[0][0][2], pA2); fma2(n023, Wp[0][0][5], pA4);
            fma2(n101, Wp[1][0][2], p02); fma2(n123, Wp[1][0][5], p04);

            fma2(n001, Wp[0][1][0], p00); fma2(n023, Wp[0][1][3], p02);
            fma2(n101, Wp[1][1][0], p10); fma2(n123, Wp[1][1][3], p12);
            fma2(n001, Wp[0][1][1], p01); fma2(n023, Wp[0][1][4], p03);
            fma2(n101, Wp[1][1][1], p11); fma2(n123, Wp[1][1][4], p13);
            fma2(n001, Wp[0][1][2], p02); fma2(n023, Wp[0][1][5], p04);
            fma2(n101, Wp[1][1][2], p12); fma2(n123, Wp[1][1][5], p14);

            fma2(n001, Wp[0][2][0], p10); fma2(n023, Wp[0][2][3], p12);
            fma2(n101, Wp[1][2][0], pB0); fma2(n123, Wp[1][2][3], pB2);
            fma2(n001, Wp[0][2][1], p11); fma2(n023, Wp[0][2][4], p13);
            fma2(n101, Wp[1][2][1], pB1); fma2(n123, Wp[1][2][4], pB3);
            fma2(n001, Wp[0][2][2], p12); fma2(n023, Wp[0][2][5], p14);
            fma2(n101, Wp[1][2][2], pB2); fma2(n123, Wp[1][2][5], pB4);

            upk(n001, y0.x, y0.y); upk(n023, y0.z, y0.w);
            upk(n101, y1.x, y1.y); upk(n123, y1.z, y1.w);

            if (s < STEPS - 1) {
                const int nb = cb ^ 1;
                *(float4*)&buf[nb][g2 + 1][col0] = y0;
                *(float4*)&buf[nb][g2 + 2][col0] = y1;
                __syncthreads();
            }
        }

        // ---- output: warps 4..11 hold the 16 exact rows (region rows 8..23)
        if ((unsigned)(warp - 4) < 8u) {
            float* ob = out + (size_t)img * IMG + (t0 + g2 - 8) * W + col0;
            *(float4*)ob       = y0;
            *(float4*)(ob + W) = y1;
        }
    }
}

extern "C" void kernel_launch(void* const* d_in, const int* in_sizes, int n_in,
                              void* d_out, int out_size)
{
    const float* x   = (const float*)d_in[0];
    const float* wgt = (const float*)d_in[1];
    float* out       = (float*)d_out;

    int sms = 148;
    cudaDeviceGetAttribute(&sms, cudaDevAttrMultiProcessorCount, 0);
    if (sms < 1) sms = 148;
    if (sms > NT) sms = NT;

    diffusion_persist_kernel<<<sms, 512>>>(x, wgt, out);
}